// round 17
// baseline (speedup 1.0000x reference)
#include <cuda_runtime.h>
#include <cstdint>

// MoE router: logits = x @ W^T via mma.sync tf32 3-term split (3xTF32).
// hi/lo split at fill time; scalar conflict-free LDS; 512 threads, 16 warps,
// intra-CTA split-K (each warp does half of each K-chunk), one merge at end.
// Output (fp32): [0,2T) top2 probs | [2T,4T) top2 indices | [4T,68T) probs.

#define TM 128
#define KC 32
#define NE 64
#define TS 36                       // tile row stride (words) -> scalar reads 1-phase
#define LG_S 68                     // logits row stride (words)

#define XH_OFF 0
#define XL_OFF (TM * TS)            // 4608
#define WH_OFF (2 * TM * TS)        // 9216
#define WL_OFF (2 * TM * TS + NE * TS)
#define SM_FLOATS (2 * TM * TS + 2 * NE * TS)   // 13824
#define SMEM_BYTES (SM_FLOATS * 4)              // 55296

__device__ __forceinline__ float tf32f(float v) {
    uint32_t h;
    asm("cvt.rna.tf32.f32 %0, %1;" : "=r"(h) : "f"(v));
    return __uint_as_float(h);
}

__device__ __forceinline__ void mma_tf32(float* d, const uint32_t* a, const uint32_t* b) {
    asm volatile(
        "mma.sync.aligned.m16n8k8.row.col.f32.tf32.tf32.f32 "
        "{%0,%1,%2,%3}, {%4,%5,%6,%7}, {%8,%9}, {%0,%1,%2,%3};"
        : "+f"(d[0]), "+f"(d[1]), "+f"(d[2]), "+f"(d[3])
        : "r"(a[0]), "r"(a[1]), "r"(a[2]), "r"(a[3]), "r"(b[0]), "r"(b[1]));
}

__device__ __forceinline__ void split4(float* hd, float* ld, float4 v) {
    float h0 = tf32f(v.x), h1 = tf32f(v.y), h2 = tf32f(v.z), h3 = tf32f(v.w);
    *(float4*)hd = make_float4(h0, h1, h2, h3);
    *(float4*)ld = make_float4(v.x - h0, v.y - h1, v.z - h2, v.w - h3);
}

__global__ __launch_bounds__(512, 1)
void moe_router_kernel(const float* __restrict__ x,
                       const float* __restrict__ w,
                       float* __restrict__ out_p,
                       float* __restrict__ out_i,
                       float* __restrict__ probs,
                       int D) {
    extern __shared__ __align__(16) float sm[];
    float* xh = sm + XH_OFF;
    float* xl = sm + XL_OFF;
    float* wh = sm + WH_OFF;
    float* wl = sm + WL_OFF;

    const int tid = threadIdx.x;
    const int wid = tid >> 5, lane = tid & 31;
    const int g = lane >> 2, tg = lane & 3;
    const int wm = wid & 3;            // token group: wm*32 .. +31
    const int wn = (wid >> 2) & 1;     // expert group: wn*32 .. +31
    const int wk2 = wid >> 3;          // K-half: k in [16*wk2, 16*wk2+16)
    const long long tBase = (long long)blockIdx.x * TM;

    // fill roles (512 threads)
    const int xr = tid >> 2, xk = (tid & 3) * 8;    // x: row 0..127, 8 consecutive k
    const int wr = tid >> 3, wk = (tid & 7) * 4;    // w: row 0..63, 4 consecutive k
    const float* xg = x + (tBase + xr) * (long long)D + xk;
    const float* wg = w + (long long)wr * D + wk;
    float* xhd = xh + xr * TS + xk;
    float* xld = xl + xr * TS + xk;
    float* whd = wh + wr * TS + wk;
    float* wld = wl + wr * TS + wk;

    float acc[2][4][4];
#pragma unroll
    for (int mt = 0; mt < 2; mt++)
#pragma unroll
        for (int nt = 0; nt < 4; nt++)
#pragma unroll
            for (int q = 0; q < 4; q++) acc[mt][nt][q] = 0.f;

    float4 rx0 = *(const float4*)(xg);
    float4 rx1 = *(const float4*)(xg + 4);
    float4 rw0 = *(const float4*)(wg);

    const int nCh = D / KC;
    for (int i = 0; i < nCh; i++) {
        split4(xhd, xld, rx0);
        split4(xhd + 4, xld + 4, rx1);
        split4(whd, wld, rw0);
        __syncthreads();

        if (i + 1 < nCh) {
            const float* xn = xg + (i + 1) * KC;
            const float* wn2 = wg + (i + 1) * KC;
            rx0 = *(const float4*)(xn);
            rx1 = *(const float4*)(xn + 4);
            rw0 = *(const float4*)(wn2);
        }

#pragma unroll
        for (int s8 = 0; s8 < 2; s8++) {
            const int kb = wk2 * 16 + 8 * s8;
            uint32_t ah[2][4], al[2][4], bh[4][2], bl[4][2];
#pragma unroll
            for (int mt = 0; mt < 2; mt++) {
                const int r0 = (wm * 32 + mt * 16 + g) * TS + kb + tg;
                const int r1 = r0 + 8 * TS;
                ah[mt][0] = __float_as_uint(xh[r0]);
                ah[mt][1] = __float_as_uint(xh[r1]);
                ah[mt][2] = __float_as_uint(xh[r0 + 4]);
                ah[mt][3] = __float_as_uint(xh[r1 + 4]);
                al[mt][0] = __float_as_uint(xl[r0]);
                al[mt][1] = __float_as_uint(xl[r1]);
                al[mt][2] = __float_as_uint(xl[r0 + 4]);
                al[mt][3] = __float_as_uint(xl[r1 + 4]);
            }
#pragma unroll
            for (int nt = 0; nt < 4; nt++) {
                const int e0 = (wn * 32 + nt * 8 + g) * TS + kb + tg;
                bh[nt][0] = __float_as_uint(wh[e0]);
                bh[nt][1] = __float_as_uint(wh[e0 + 4]);
                bl[nt][0] = __float_as_uint(wl[e0]);
                bl[nt][1] = __float_as_uint(wl[e0 + 4]);
            }
#pragma unroll
            for (int mt = 0; mt < 2; mt++)
#pragma unroll
                for (int nt = 0; nt < 4; nt++) {
                    mma_tf32(acc[mt][nt], al[mt], bh[nt]);
                    mma_tf32(acc[mt][nt], ah[mt], bl[nt]);
                    mma_tf32(acc[mt][nt], ah[mt], bh[nt]);
                }
        }
        __syncthreads();
    }

    // ---- split-K merge + logits -> smem [128][68] ----
    float* lg = sm;
    if (wk2 == 1) {
#pragma unroll
        for (int mt = 0; mt < 2; mt++)
#pragma unroll
            for (int nt = 0; nt < 4; nt++) {
                const int row = wm * 32 + mt * 16 + g;
                const int col = wn * 32 + nt * 8 + 2 * tg;
                *(float2*)&lg[row * LG_S + col] = make_float2(acc[mt][nt][0], acc[mt][nt][1]);
                *(float2*)&lg[(row + 8) * LG_S + col] = make_float2(acc[mt][nt][2], acc[mt][nt][3]);
            }
    }
    __syncthreads();
    if (wk2 == 0) {
#pragma unroll
        for (int mt = 0; mt < 2; mt++)
#pragma unroll
            for (int nt = 0; nt < 4; nt++) {
                const int row = wm * 32 + mt * 16 + g;
                const int col = wn * 32 + nt * 8 + 2 * tg;
                float2 p0 = *(const float2*)&lg[row * LG_S + col];
                float2 p1 = *(const float2*)&lg[(row + 8) * LG_S + col];
                *(float2*)&lg[row * LG_S + col] =
                    make_float2(acc[mt][nt][0] + p0.x, acc[mt][nt][1] + p0.y);
                *(float2*)&lg[(row + 8) * LG_S + col] =
                    make_float2(acc[mt][nt][2] + p1.x, acc[mt][nt][3] + p1.y);
            }
    }
    __syncthreads();

    // warps 0-3: one token per lane; softmax + top-2 in registers
    if (wid < 4) {
        const int tl = wid * 32 + lane;
        float* row = &lg[tl * LG_S];
        float e[64];
#pragma unroll
        for (int c = 0; c < 64; c += 4) {
            float4 v = *(const float4*)(row + c);
            e[c] = v.x; e[c + 1] = v.y; e[c + 2] = v.z; e[c + 3] = v.w;
        }
        float m = e[0];
#pragma unroll
        for (int c = 1; c < 64; c++) m = fmaxf(m, e[c]);
        float sum = 0.f;
#pragma unroll
        for (int c = 0; c < 64; c++) { e[c] = __expf(e[c] - m); sum += e[c]; }
        float a1 = -1.f, a2 = -1.f;
        int i1 = 0, i2 = 0;
#pragma unroll
        for (int c = 0; c < 64; c++) {
            float p = e[c];
            if (p > a1)      { a2 = a1; i2 = i1; a1 = p; i1 = c; }
            else if (p > a2) { a2 = p; i2 = c; }
        }
        const float inv = 1.0f / sum;
#pragma unroll
        for (int c = 0; c < 64; c += 4)
            *(float4*)(row + c) = make_float4(e[c] * inv, e[c + 1] * inv,
                                              e[c + 2] * inv, e[c + 3] * inv);
        const long long t = tBase + tl;
        const float sn = a1 + a2;
        *(float2*)(out_p + t * 2) = make_float2(a1 / sn, a2 / sn);
        *(float2*)(out_i + t * 2) = make_float2((float)i1, (float)i2);
    }
    __syncthreads();

    // coalesced probs writeback: 2048 float4 per CTA, 512 threads
    {
        float* pg = probs + tBase * 64;
#pragma unroll
        for (int j = 0; j < 4; j++) {
            const int fidx = tid + 512 * j;
            const int trow = fidx >> 4, cc = fidx & 15;
            *(float4*)(pg + (long long)fidx * 4) = *(const float4*)&lg[trow * LG_S + cc * 4];
        }
    }
}

extern "C" void kernel_launch(void* const* d_in, const int* in_sizes, int n_in,
                              void* d_out, int out_size) {
    const float* x = (const float*)d_in[0];
    const float* w = (const float*)d_in[1];
    float* out = (float*)d_out;

    const long long T = (long long)out_size / 68;
    const int D = (int)((long long)in_sizes[0] / T);

    float* out_p = out;           // [T,2]
    float* out_i = out + 2 * T;   // [T,2]
    float* probs = out + 4 * T;   // [T,64]

    cudaFuncSetAttribute(moe_router_kernel,
                         cudaFuncAttributeMaxDynamicSharedMemorySize, SMEM_BYTES);
    moe_router_kernel<<<(int)(T / TM), 512, SMEM_BYTES>>>(x, w, out_p, out_i, probs, D);
}